// round 2
// baseline (speedup 1.0000x reference)
#include <cuda_runtime.h>
#include <math.h>

#define BSZ   8192
#define NBLK  8
#define HDIM  256
#define DDIM  256
#define DKIN  16
#define DVIN  32
#define NHC   4
#define DKC   8
#define KACT  4

// ---------------- device scratch (static, no allocation) ----------------
__device__ float g_mask  [BSZ * NBLK];                 // (B,N)
__device__ float g_inputs[BSZ * NBLK * DVIN];          // (B,N,32), mask applied
__device__ float g_hsnew [BSZ * NBLK * HDIM];          // (B,N,256)
__device__ float g_q2    [BSZ * NBLK * 32];            // (B,N,32)
__device__ float g_k2    [BSZ * NBLK * 32];            // (B,N,32)
__device__ float g_att   [BSZ * NHC * NBLK * NBLK];    // (B,4,8,8)
__device__ float g_v2    [BSZ * NBLK * 1024];          // (B,m,1024)
__device__ float g_ctx   [BSZ * NBLK * 1024];          // (B,n,1024)

// ================= Kernel 1: gating attention, mask, inputs ==============
// one warp per batch element; block = 8 warps
__global__ __launch_bounds__(256) void k1_gating(
    const float* __restrict__ x1, const float* __restrict__ x2,
    const float* __restrict__ hs,
    const float* __restrict__ Wkey, const float* __restrict__ bkey,
    const float* __restrict__ Wval, const float* __restrict__ bval,
    const float* __restrict__ Wq)
{
    const int w    = threadIdx.x >> 5;
    const int lane = threadIdx.x & 31;
    const int b    = blockIdx.x * 8 + w;

    __shared__ float sKL[8][48];
    __shared__ float sVL[8][96];
    __shared__ float sQL[8][128];
    __shared__ float sS [8][24];
    __shared__ float sM [8][8];

    // kL[s][j] = bkey[j] + x_s . Wkey[:,j]   (x_2 == 0)
    for (int o = lane; o < 48; o += 32) {
        int s = o >> 4, j = o & 15;
        float acc = bkey[j];
        if (s < 2) {
            const float* xp = s ? (x2 + b * DDIM) : (x1 + b * DDIM);
            #pragma unroll 8
            for (int d = 0; d < DDIM; d++) acc += xp[d] * Wkey[d * DKIN + j];
        }
        sKL[w][o] = acc;
    }
    // vL[s][j]
    for (int o = lane; o < 96; o += 32) {
        int s = o >> 5, j = o & 31;
        float acc = bval[j];
        if (s < 2) {
            const float* xp = s ? (x2 + b * DDIM) : (x1 + b * DDIM);
            #pragma unroll 8
            for (int d = 0; d < DDIM; d++) acc += xp[d] * Wval[d * DVIN + j];
        }
        sVL[w][o] = acc;
    }
    // qL[n][j] = hs[b,n,:] . Wq[n,:,j]
    for (int o = lane; o < 128; o += 32) {
        int nn = o >> 4, j = o & 15;
        const float* hp = hs + (b * NBLK + nn) * HDIM;
        const float* wp = Wq + nn * HDIM * DKIN + j;
        float acc = 0.f;
        #pragma unroll 8
        for (int d = 0; d < DDIM; d++) acc += hp[d] * wp[d * DKIN];
        sQL[w][o] = acc;
    }
    __syncwarp();

    // scores[n][s] = 0.25 * qL[n].kL[s]
    for (int o = lane; o < 24; o += 32) {
        int nn = o / 3, s = o % 3;
        float acc = 0.f;
        #pragma unroll
        for (int j = 0; j < 16; j++) acc += sQL[w][nn * 16 + j] * sKL[w][s * 16 + j];
        sS[w][o] = acc * 0.25f;
    }
    __syncwarp();

    // mask: top (N-KACT) null scores are blocked (ties -> lower index wins, as lax.top_k)
    if (lane < 8) {
        float nu = sS[w][lane * 3 + 2];
        int rank = 0;
        #pragma unroll
        for (int n2 = 0; n2 < 8; n2++) {
            float nu2 = sS[w][n2 * 3 + 2];
            rank += (nu2 > nu) || (nu2 == nu && n2 < lane);
        }
        float m = (rank < (NBLK - KACT)) ? 0.f : 1.f;
        sM[w][lane] = m;
        g_mask[b * NBLK + lane] = m;
    }
    __syncwarp();

    // probs (softmax over 3) then inputs = mask * probs . vL
    for (int o = lane; o < 256; o += 32) {
        int nn = o >> 5, j = o & 31;
        float s0 = sS[w][nn * 3 + 0];
        float s1 = sS[w][nn * 3 + 1];
        float s2 = sS[w][nn * 3 + 2];
        float mx = fmaxf(s0, fmaxf(s1, s2));
        float e0 = expf(s0 - mx), e1 = expf(s1 - mx), e2 = expf(s2 - mx);
        float inv = 1.f / (e0 + e1 + e2);
        float val = (e0 * sVL[w][j] + e1 * sVL[w][32 + j] + e2 * sVL[w][64 + j])
                    * inv * sM[w][nn];
        g_inputs[(b * NBLK + nn) * DVIN + j] = val;
    }
}

// ================= Kernel 2: fused GRU (gate_x + gate_h GEMM + epilogue) ==
// grid (128 btiles, 8 htiles, 8 n), 256 threads; tile: 64 rows x 32 h-cols
// each thread: 4 rows x (3 gate groups x 2 h) accumulators for gx and gh
__global__ __launch_bounds__(256) void k2_gru(
    const float* __restrict__ hs,
    const float* __restrict__ Wx2h,
    const float* __restrict__ Wh2h)
{
    const int n  = blockIdx.z;
    const int b0 = blockIdx.x * 64;
    const int h0 = blockIdx.y * 32;
    const int tid = threadIdx.x;
    const int tx = tid & 15, ty = tid >> 4;

    __shared__ float sA[64][33];
    __shared__ float sW[32][96];

    float gx[4][3][2], gh[4][3][2];
    #pragma unroll
    for (int i = 0; i < 4; i++)
        #pragma unroll
        for (int g = 0; g < 3; g++) { gx[i][g][0]=gx[i][g][1]=0.f; gh[i][g][0]=gh[i][g][1]=0.f; }

    // ---- gate_x: K = 32 (inputs already mask-scaled) ----
    for (int l = tid; l < 64 * 32; l += 256) {
        int row = l >> 5, k = l & 31;
        sA[row][k] = g_inputs[((b0 + row) * NBLK + n) * DVIN + k];
    }
    for (int l = tid; l < 32 * 96; l += 256) {
        int k = l / 96, c = l % 96;
        int g = c >> 5, hh = c & 31;
        sW[k][c] = Wx2h[(n * 32 + k) * 768 + g * 256 + h0 + hh];
    }
    __syncthreads();
    #pragma unroll
    for (int k = 0; k < 32; k++) {
        float a0 = sA[ty][k], a1 = sA[ty + 16][k], a2 = sA[ty + 32][k], a3 = sA[ty + 48][k];
        #pragma unroll
        for (int g = 0; g < 3; g++) {
            float2 wv = *(const float2*)&sW[k][g * 32 + 2 * tx];
            gx[0][g][0] += a0 * wv.x; gx[0][g][1] += a0 * wv.y;
            gx[1][g][0] += a1 * wv.x; gx[1][g][1] += a1 * wv.y;
            gx[2][g][0] += a2 * wv.x; gx[2][g][1] += a2 * wv.y;
            gx[3][g][0] += a3 * wv.x; gx[3][g][1] += a3 * wv.y;
        }
    }
    __syncthreads();

    // ---- gate_h: K = 256 ----
    for (int kt = 0; kt < 256; kt += 32) {
        for (int l = tid; l < 64 * 32; l += 256) {
            int row = l >> 5, k = l & 31;
            sA[row][k] = hs[((b0 + row) * NBLK + n) * HDIM + kt + k];
        }
        for (int l = tid; l < 32 * 96; l += 256) {
            int k = l / 96, c = l % 96;
            int g = c >> 5, hh = c & 31;
            sW[k][c] = Wh2h[(n * 256 + kt + k) * 768 + g * 256 + h0 + hh];
        }
        __syncthreads();
        #pragma unroll
        for (int k = 0; k < 32; k++) {
            float a0 = sA[ty][k], a1 = sA[ty + 16][k], a2 = sA[ty + 32][k], a3 = sA[ty + 48][k];
            #pragma unroll
            for (int g = 0; g < 3; g++) {
                float2 wv = *(const float2*)&sW[k][g * 32 + 2 * tx];
                gh[0][g][0] += a0 * wv.x; gh[0][g][1] += a0 * wv.y;
                gh[1][g][0] += a1 * wv.x; gh[1][g][1] += a1 * wv.y;
                gh[2][g][0] += a2 * wv.x; gh[2][g][1] += a2 * wv.y;
                gh[3][g][0] += a3 * wv.x; gh[3][g][1] += a3 * wv.y;
            }
        }
        __syncthreads();
    }

    // ---- epilogue: GRU update ----
    #pragma unroll
    for (int i = 0; i < 4; i++) {
        int b = b0 + ty + 16 * i;
        #pragma unroll
        for (int p = 0; p < 2; p++) {
            int h = h0 + 2 * tx + p;
            float r  = 1.f / (1.f + expf(-(gx[i][0][p] + gh[i][0][p])));
            float z  = 1.f / (1.f + expf(-(gx[i][1][p] + gh[i][1][p])));
            float nv = tanhf(gx[i][2][p] + r * gh[i][2][p]);
            int idx = (b * NBLK + n) * HDIM + h;
            float hold = hs[idx];
            g_hsnew[idx] = nv + z * (hold - nv);
        }
    }
}

// ================= Kernel 3a1: q2/k2 projection GEMM ======================
// grid (128, 1, 8); tile 64 rows x 64 cols (cols 0..31 -> Wq_, 32..63 -> Wk_)
__global__ __launch_bounds__(256) void k3a1_qk(
    const float* __restrict__ Wq_, const float* __restrict__ Wk_)
{
    const int n  = blockIdx.z;
    const int b0 = blockIdx.x * 64;
    const int tid = threadIdx.x;
    const int tx = tid & 15, ty = tid >> 4;

    __shared__ float sA[64][33];
    __shared__ float sW[32][64];

    float acc[4][4] = {};
    for (int kt = 0; kt < 256; kt += 32) {
        for (int l = tid; l < 64 * 32; l += 256) {
            int row = l >> 5, k = l & 31;
            sA[row][k] = g_hsnew[((b0 + row) * NBLK + n) * HDIM + kt + k];
        }
        for (int l = tid; l < 32 * 64; l += 256) {
            int k = l >> 6, c = l & 63;
            sW[k][c] = (c < 32) ? Wq_[(n * 256 + kt + k) * 32 + c]
                                : Wk_[(n * 256 + kt + k) * 32 + (c - 32)];
        }
        __syncthreads();
        #pragma unroll
        for (int k = 0; k < 32; k++) {
            float a0 = sA[ty][k], a1 = sA[ty + 16][k], a2 = sA[ty + 32][k], a3 = sA[ty + 48][k];
            float4 wv = *(const float4*)&sW[k][tx * 4];
            acc[0][0]+=a0*wv.x; acc[0][1]+=a0*wv.y; acc[0][2]+=a0*wv.z; acc[0][3]+=a0*wv.w;
            acc[1][0]+=a1*wv.x; acc[1][1]+=a1*wv.y; acc[1][2]+=a1*wv.z; acc[1][3]+=a1*wv.w;
            acc[2][0]+=a2*wv.x; acc[2][1]+=a2*wv.y; acc[2][2]+=a2*wv.z; acc[2][3]+=a2*wv.w;
            acc[3][0]+=a3*wv.x; acc[3][1]+=a3*wv.y; acc[3][2]+=a3*wv.z; acc[3][3]+=a3*wv.w;
        }
        __syncthreads();
    }
    #pragma unroll
    for (int i = 0; i < 4; i++) {
        int b = b0 + ty + 16 * i;
        float4 v = make_float4(acc[i][0], acc[i][1], acc[i][2], acc[i][3]);
        if (tx < 8) *(float4*)&g_q2[(b * NBLK + n) * 32 + tx * 4] = v;
        else        *(float4*)&g_k2[(b * NBLK + n) * 32 + (tx - 8) * 4] = v;
    }
}

// ================= Kernel 3a2: 4-head 8x8 attention + softmax + mask ======
__global__ __launch_bounds__(256) void k3a2_att()
{
    const int w = threadIdx.x >> 5, lane = threadIdx.x & 31;
    const int b = blockIdx.x * 8 + w;

    __shared__ float sQ[8][256];
    __shared__ float sK[8][256];
    for (int l = lane; l < 256; l += 32) {
        sQ[w][l] = g_q2[b * 256 + l];
        sK[w][l] = g_k2[b * 256 + l];
    }
    __syncwarp();

    const int h = lane >> 3, nq = lane & 7;   // 32 (h, n) pairs, one per lane
    float sc[8], mx = -1e30f;
    #pragma unroll
    for (int m = 0; m < 8; m++) {
        float s = 0.f;
        #pragma unroll
        for (int dk = 0; dk < 8; dk++)
            s += sQ[w][nq * 32 + h * 8 + dk] * sK[w][m * 32 + h * 8 + dk];
        s *= 0.35355339059327373f;   // DK_C^-0.5
        sc[m] = s;
        mx = fmaxf(mx, s);
    }
    float den = 0.f;
    #pragma unroll
    for (int m = 0; m < 8; m++) { sc[m] = expf(sc[m] - mx); den += sc[m]; }
    float scale = g_mask[b * NBLK + nq] / den;
    #pragma unroll
    for (int m = 0; m < 8; m++)
        g_att[((b * NHC + h) * NBLK + nq) * NBLK + m] = sc[m] * scale;
}

// ================= Kernel 3b: v2 = hs_new @ Wv_ ===========================
// grid (128, 16, 8); tile 64 x 64, K=256
__global__ __launch_bounds__(256) void k3b_v2(const float* __restrict__ Wv_)
{
    const int n  = blockIdx.z;
    const int b0 = blockIdx.x * 64;
    const int o0 = blockIdx.y * 64;
    const int tid = threadIdx.x;
    const int tx = tid & 15, ty = tid >> 4;

    __shared__ float sA[64][33];
    __shared__ float sW[32][64];

    float acc[4][4] = {};
    for (int kt = 0; kt < 256; kt += 32) {
        for (int l = tid; l < 64 * 32; l += 256) {
            int row = l >> 5, k = l & 31;
            sA[row][k] = g_hsnew[((b0 + row) * NBLK + n) * HDIM + kt + k];
        }
        for (int l = tid; l < 32 * 64; l += 256) {
            int k = l >> 6, c = l & 63;
            sW[k][c] = Wv_[(n * 256 + kt + k) * 1024 + o0 + c];
        }
        __syncthreads();
        #pragma unroll
        for (int k = 0; k < 32; k++) {
            float a0 = sA[ty][k], a1 = sA[ty + 16][k], a2 = sA[ty + 32][k], a3 = sA[ty + 48][k];
            float4 wv = *(const float4*)&sW[k][tx * 4];
            acc[0][0]+=a0*wv.x; acc[0][1]+=a0*wv.y; acc[0][2]+=a0*wv.z; acc[0][3]+=a0*wv.w;
            acc[1][0]+=a1*wv.x; acc[1][1]+=a1*wv.y; acc[1][2]+=a1*wv.z; acc[1][3]+=a1*wv.w;
            acc[2][0]+=a2*wv.x; acc[2][1]+=a2*wv.y; acc[2][2]+=a2*wv.z; acc[2][3]+=a2*wv.w;
            acc[3][0]+=a3*wv.x; acc[3][1]+=a3*wv.y; acc[3][2]+=a3*wv.z; acc[3][3]+=a3*wv.w;
        }
        __syncthreads();
    }
    #pragma unroll
    for (int i = 0; i < 4; i++) {
        int b = b0 + ty + 16 * i;
        float4 v = make_float4(acc[i][0], acc[i][1], acc[i][2], acc[i][3]);
        *(float4*)&g_v2[(b * NBLK + n) * 1024 + o0 + tx * 4] = v;
    }
}

// ================= Kernel 3c: ctx = att @ v2 (per-b, smem resident) =======
__global__ __launch_bounds__(256) void k3c_ctx()
{
    const int b = blockIdx.x;
    __shared__ float sV[8 * 1024];
    __shared__ float sAtt[256];

    const float* vb = g_v2 + b * 8192;
    for (int l = threadIdx.x; l < 8192; l += 256) sV[l] = vb[l];
    sAtt[threadIdx.x] = g_att[b * 256 + threadIdx.x];
    __syncthreads();

    float* cb = g_ctx + b * 8192;
    for (int l = threadIdx.x; l < 8192; l += 256) {
        int nq = l >> 10, c = l & 1023, g = c >> 8;
        const float* ap = &sAtt[(g * 8 + nq) * 8];
        float acc = 0.f;
        #pragma unroll
        for (int m = 0; m < 8; m++) acc += ap[m] * sV[m * 1024 + c];
        cb[l] = acc;
    }
}

// ================= Kernel 3d: out = ctx @ Wout + hs_new, masked mix ======
// grid (128, 4, 8); tile 64 x 64, K=1024
__global__ __launch_bounds__(256) void k3d_out(
    const float* __restrict__ Wout, const float* __restrict__ hs,
    float* __restrict__ out)
{
    const int n  = blockIdx.z;
    const int b0 = blockIdx.x * 64;
    const int o0 = blockIdx.y * 64;
    const int tid = threadIdx.x;
    const int tx = tid & 15, ty = tid >> 4;

    __shared__ float sA[64][33];
    __shared__ float sW[32][64];

    float acc[4][4] = {};
    for (int kt = 0; kt < 1024; kt += 32) {
        for (int l = tid; l < 64 * 32; l += 256) {
            int row = l >> 5, k = l & 31;
            sA[row][k] = g_ctx[((b0 + row) * NBLK + n) * 1024 + kt + k];
        }
        for (int l = tid; l < 32 * 64; l += 256) {
            int k = l >> 6, c = l & 63;
            sW[k][c] = Wout[(n * 1024 + kt + k) * 256 + o0 + c];
        }
        __syncthreads();
        #pragma unroll
        for (int k = 0; k < 32; k++) {
            float a0 = sA[ty][k], a1 = sA[ty + 16][k], a2 = sA[ty + 32][k], a3 = sA[ty + 48][k];
            float4 wv = *(const float4*)&sW[k][tx * 4];
            acc[0][0]+=a0*wv.x; acc[0][1]+=a0*wv.y; acc[0][2]+=a0*wv.z; acc[0][3]+=a0*wv.w;
            acc[1][0]+=a1*wv.x; acc[1][1]+=a1*wv.y; acc[1][2]+=a1*wv.z; acc[1][3]+=a1*wv.w;
            acc[2][0]+=a2*wv.x; acc[2][1]+=a2*wv.y; acc[2][2]+=a2*wv.z; acc[2][3]+=a2*wv.w;
            acc[3][0]+=a3*wv.x; acc[3][1]+=a3*wv.y; acc[3][2]+=a3*wv.z; acc[3][3]+=a3*wv.w;
        }
        __syncthreads();
    }
    #pragma unroll
    for (int i = 0; i < 4; i++) {
        int b = b0 + ty + 16 * i;
        float m = g_mask[b * NBLK + n];
        int idx = (b * NBLK + n) * HDIM + o0 + tx * 4;
        float4 hn = *(const float4*)&g_hsnew[idx];
        float4 ho = *(const float4*)&hs[idx];
        float4 r;
        r.x = m * (acc[i][0] + hn.x) + (1.f - m) * ho.x;
        r.y = m * (acc[i][1] + hn.y) + (1.f - m) * ho.y;
        r.z = m * (acc[i][2] + hn.z) + (1.f - m) * ho.z;
        r.w = m * (acc[i][3] + hn.w) + (1.f - m) * ho.w;
        *(float4*)&out[idx] = r;
    }
}

// =========================== launch ======================================
extern "C" void kernel_launch(void* const* d_in, const int* in_sizes, int n_in,
                              void* d_out, int out_size)
{
    const float* x1   = (const float*)d_in[0];
    const float* x2   = (const float*)d_in[1];
    const float* hs   = (const float*)d_in[2];
    const float* Wkey = (const float*)d_in[3];
    const float* bkey = (const float*)d_in[4];
    const float* Wval = (const float*)d_in[5];
    const float* bval = (const float*)d_in[6];
    const float* Wq   = (const float*)d_in[7];
    const float* Wq_  = (const float*)d_in[8];
    const float* Wk_  = (const float*)d_in[9];
    const float* Wv_  = (const float*)d_in[10];
    const float* Wout = (const float*)d_in[11];
    const float* Wx2h = (const float*)d_in[12];
    const float* Wh2h = (const float*)d_in[13];
    float* out = (float*)d_out;

    k1_gating<<<BSZ / 8, 256>>>(x1, x2, hs, Wkey, bkey, Wval, bval, Wq);
    k2_gru   <<<dim3(BSZ / 64, HDIM / 32, NBLK), 256>>>(hs, Wx2h, Wh2h);
    k3a1_qk  <<<dim3(BSZ / 64, 1, NBLK), 256>>>(Wq_, Wk_);
    k3a2_att <<<BSZ / 8, 256>>>();
    k3b_v2   <<<dim3(BSZ / 64, 16, NBLK), 256>>>(Wv_);
    k3c_ctx  <<<BSZ, 256>>>();
    k3d_out  <<<dim3(BSZ / 64, 4, NBLK), 256>>>(Wout, hs, out);
}